// round 3
// baseline (speedup 1.0000x reference)
#include <cuda_runtime.h>

#define BB 32
#define CC 128
#define TLEN 16000
#define TTILE 64
#define KC 16

// Scratch (allocation-guard-safe __device__ globals)
__device__ float g_wt[3 * CC * 2 * CC];       // transposed weights: [conv][cin][tap][cout]
__device__ float g_o[(size_t)BB * CC * TLEN]; // gated activation output

// ---------------------------------------------------------------------------
// Transpose weights from [cout][cin][k] to [cin][k][cout] so smem staging in
// the GEMM kernels is fully coalesced (avoids 8x L2 sector amplification).
// ---------------------------------------------------------------------------
__global__ void k_transpose(const float* __restrict__ wf,
                            const float* __restrict__ wg,
                            const float* __restrict__ ws) {
    int idx = blockIdx.x * 256 + threadIdx.x;
    const int per = CC * 2 * CC; // 32768
    if (idx >= 3 * per) return;
    int conv = idx / per;
    int r = idx - conv * per;
    int cin  = r / (2 * CC);
    int k    = (r / CC) & 1;
    int cout = r & (CC - 1);
    const float* src = (conv == 0) ? wf : ((conv == 1) ? wg : ws);
    g_wt[idx] = src[cout * (CC * 2) + cin * 2 + k];
}

// ---------------------------------------------------------------------------
// Kernel 1: o = tanh(conv_dil2(x, Wf)) * sigmoid(conv_dil2(x, Wg))
// Block = (batch b, 64-wide t tile). 256 threads: tx in [0,32) -> 4 couts,
// ty in [0,8) -> 8 t positions. 64 fp32 accumulators per thread.
// ---------------------------------------------------------------------------
__global__ __launch_bounds__(256, 2) void k_fg(const float* __restrict__ x) {
    extern __shared__ float sm[];
    float* xs  = sm;                    // [128][66], j=0 <-> t = tbase-2
    float* wsf = sm + CC * 66;          // [KC][2][128]
    float* wsg = wsf + KC * 2 * CC;     // [KC][2][128]

    const int b     = blockIdx.y;
    const int tbase = blockIdx.x * TTILE;
    const int tid   = threadIdx.x;
    const int tx    = tid & 31;
    const int ty    = tid >> 5;

    const float* xb = x + (size_t)b * CC * TLEN;

    // Stage x tile (halo of 2 on the left, causal zero pad)
    for (int idx = tid; idx < CC * 66; idx += 256) {
        int cin = idx / 66;
        int j   = idx - cin * 66;
        int t   = tbase - 2 + j;
        xs[idx] = (t >= 0) ? xb[cin * TLEN + t] : 0.f;
    }

    float f[4][8], g[4][8];
#pragma unroll
    for (int i = 0; i < 4; i++)
#pragma unroll
        for (int j = 0; j < 8; j++) { f[i][j] = 0.f; g[i][j] = 0.f; }

    for (int cc = 0; cc < CC; cc += KC) {
        __syncthreads();
        const float* gf = g_wt + 0 * CC * 2 * CC + cc * 2 * CC;
        const float* gg = g_wt + 1 * CC * 2 * CC + cc * 2 * CC;
        for (int idx = tid; idx < KC * 2 * CC; idx += 256) {
            wsf[idx] = gf[idx];
            wsg[idx] = gg[idx];
        }
        __syncthreads();

#pragma unroll
        for (int ci = 0; ci < KC; ci++) {
            const int cin = cc + ci;
            float xv[10];
            const float* xrow = xs + cin * 66 + ty * 8;
#pragma unroll
            for (int j = 0; j < 10; j++) xv[j] = xrow[j];

            float4 wf0 = *(const float4*)&wsf[(ci * 2 + 0) * CC + tx * 4];
            float4 wf1 = *(const float4*)&wsf[(ci * 2 + 1) * CC + tx * 4];
            float4 wg0 = *(const float4*)&wsg[(ci * 2 + 0) * CC + tx * 4];
            float4 wg1 = *(const float4*)&wsg[(ci * 2 + 1) * CC + tx * 4];

#pragma unroll
            for (int tt = 0; tt < 8; tt++) {
                float x0 = xv[tt];       // tap 0: t - 2
                float x1 = xv[tt + 2];   // tap 1: t
                f[0][tt] += wf0.x * x0; f[0][tt] += wf1.x * x1;
                f[1][tt] += wf0.y * x0; f[1][tt] += wf1.y * x1;
                f[2][tt] += wf0.z * x0; f[2][tt] += wf1.z * x1;
                f[3][tt] += wf0.w * x0; f[3][tt] += wf1.w * x1;
                g[0][tt] += wg0.x * x0; g[0][tt] += wg1.x * x1;
                g[1][tt] += wg0.y * x0; g[1][tt] += wg1.y * x1;
                g[2][tt] += wg0.z * x0; g[2][tt] += wg1.z * x1;
                g[3][tt] += wg0.w * x0; g[3][tt] += wg1.w * x1;
            }
        }
    }

    // Epilogue: gated activation, vectorized store
    float* ob = g_o + (size_t)b * CC * TLEN;
    const int t0 = tbase + ty * 8;
#pragma unroll
    for (int i = 0; i < 4; i++) {
        const int cout = tx * 4 + i;
        float ov[8];
#pragma unroll
        for (int tt = 0; tt < 8; tt++) {
            float fv = tanhf(f[i][tt]);
            float gv = 1.f / (1.f + __expf(-g[i][tt]));
            ov[tt] = fv * gv;
        }
        float* dst = ob + cout * TLEN + t0;
        *(float4*)(dst)     = make_float4(ov[0], ov[1], ov[2], ov[3]);
        *(float4*)(dst + 4) = make_float4(ov[4], ov[5], ov[6], ov[7]);
    }
}

// ---------------------------------------------------------------------------
// Kernel 2: skip = conv_dil1(o, Ws); out = skip + x. Writes both outputs.
// ---------------------------------------------------------------------------
__global__ __launch_bounds__(256, 2) void k_skip(const float* __restrict__ x,
                                                 float* __restrict__ out,
                                                 float* __restrict__ skip) {
    extern __shared__ float sm[];
    float* os  = sm;                 // [128][65], j=0 <-> t = tbase-1
    float* wss = sm + CC * 65;       // [KC][2][128]

    const int b     = blockIdx.y;
    const int tbase = blockIdx.x * TTILE;
    const int tid   = threadIdx.x;
    const int tx    = tid & 31;
    const int ty    = tid >> 5;

    const float* ob = g_o + (size_t)b * CC * TLEN;

    for (int idx = tid; idx < CC * 65; idx += 256) {
        int cin = idx / 65;
        int j   = idx - cin * 65;
        int t   = tbase - 1 + j;
        os[idx] = (t >= 0) ? ob[cin * TLEN + t] : 0.f;
    }

    float s[4][8];
#pragma unroll
    for (int i = 0; i < 4; i++)
#pragma unroll
        for (int j = 0; j < 8; j++) s[i][j] = 0.f;

    for (int cc = 0; cc < CC; cc += KC) {
        __syncthreads();
        const float* gs = g_wt + 2 * CC * 2 * CC + cc * 2 * CC;
        for (int idx = tid; idx < KC * 2 * CC; idx += 256) wss[idx] = gs[idx];
        __syncthreads();

#pragma unroll
        for (int ci = 0; ci < KC; ci++) {
            const int cin = cc + ci;
            float xv[9];
            const float* orow = os + cin * 65 + ty * 8;
#pragma unroll
            for (int j = 0; j < 9; j++) xv[j] = orow[j];

            float4 w0 = *(const float4*)&wss[(ci * 2 + 0) * CC + tx * 4];
            float4 w1 = *(const float4*)&wss[(ci * 2 + 1) * CC + tx * 4];

#pragma unroll
            for (int tt = 0; tt < 8; tt++) {
                float x0 = xv[tt];       // tap 0: t - 1
                float x1 = xv[tt + 1];   // tap 1: t
                s[0][tt] += w0.x * x0; s[0][tt] += w1.x * x1;
                s[1][tt] += w0.y * x0; s[1][tt] += w1.y * x1;
                s[2][tt] += w0.z * x0; s[2][tt] += w1.z * x1;
                s[3][tt] += w0.w * x0; s[3][tt] += w1.w * x1;
            }
        }
    }

    // Epilogue: residual add + write both tuple outputs
    const float* xb = x + (size_t)b * CC * TLEN;
    const int t0 = tbase + ty * 8;
#pragma unroll
    for (int i = 0; i < 4; i++) {
        const int cout = tx * 4 + i;
        const int off  = (b * CC + cout) * TLEN + t0;
        float4 xr0 = *(const float4*)&xb[cout * TLEN + t0];
        float4 xr1 = *(const float4*)&xb[cout * TLEN + t0 + 4];
        float4 s0 = make_float4(s[i][0], s[i][1], s[i][2], s[i][3]);
        float4 s1 = make_float4(s[i][4], s[i][5], s[i][6], s[i][7]);
        *(float4*)&skip[off]     = s0;
        *(float4*)&skip[off + 4] = s1;
        *(float4*)&out[off]      = make_float4(s0.x + xr0.x, s0.y + xr0.y,
                                               s0.z + xr0.z, s0.w + xr0.w);
        *(float4*)&out[off + 4]  = make_float4(s1.x + xr1.x, s1.y + xr1.y,
                                               s1.z + xr1.z, s1.w + xr1.w);
    }
}

extern "C" void kernel_launch(void* const* d_in, const int* in_sizes, int n_in,
                              void* d_out, int out_size) {
    const float* x  = (const float*)d_in[0];
    const float* wf = (const float*)d_in[1];
    const float* wg = (const float*)d_in[2];
    const float* ws = (const float*)d_in[3];
    // d_in[4] = dilation (int32), fixed at 2 for this problem's shapes.

    float* out  = (float*)d_out;
    float* skip = out + (size_t)BB * CC * TLEN;

    const int SMEM1 = (CC * 66 + 2 * KC * 2 * CC) * sizeof(float); // 66560 B
    const int SMEM2 = (CC * 65 + KC * 2 * CC) * sizeof(float);     // 49664 B
    cudaFuncSetAttribute(k_fg,   cudaFuncAttributeMaxDynamicSharedMemorySize, SMEM1);
    cudaFuncSetAttribute(k_skip, cudaFuncAttributeMaxDynamicSharedMemorySize, SMEM2);

    k_transpose<<<(3 * CC * 2 * CC + 255) / 256, 256>>>(wf, wg, ws);

    dim3 grid(TLEN / TTILE, BB);
    k_fg<<<grid, 256, SMEM1>>>(x);
    k_skip<<<grid, 256, SMEM2>>>(x, out, skip);
}

// round 5
// speedup vs baseline: 1.6915x; 1.6915x over previous
#include <cuda_runtime.h>
#include <cstdint>

#define BB 32
#define CC 128
#define TLEN 16000
#define NT 64
#define KTOT 256
#define NCHUNK 8
#define MSTR 36   // A smem row stride (floats): banks (4*grp+qc) -> conflict-free
#define BSTR 72   // B smem row stride (floats): banks (8*qc+grp) -> conflict-free

// smem sizes (floats)
#define FG_SMEM_F (2 * 128 * MSTR + 32 * BSTR)   // 11520 -> 46080 B
#define SK_SMEM_F (8 * 32 * 33)                  // epilogue tiles dominate: 8448 -> 33792 B
#define SMEM1 (FG_SMEM_F * 4)
#define SMEM2 (SK_SMEM_F * 4)

__device__ float g_wtA[3 * CC * KTOT];        // [conv][cout][k = tap*128+cin], tf32-rounded
__device__ float g_o[(size_t)BB * CC * TLEN]; // gated output, tf32-rounded

// ---------------- helpers ----------------
__device__ __forceinline__ uint32_t tf32u(float x) {
    uint32_t u; asm("cvt.rna.tf32.f32 %0, %1;" : "=r"(u) : "f"(x)); return u;
}
__device__ __forceinline__ float rtf32(float x) { return __uint_as_float(tf32u(x)); }

__device__ __forceinline__ void mma_tf32(float* d, const uint32_t* a, const uint32_t* b) {
    asm volatile(
        "mma.sync.aligned.m16n8k8.row.col.f32.tf32.tf32.f32 "
        "{%0,%1,%2,%3}, {%4,%5,%6,%7}, {%8,%9}, {%0,%1,%2,%3};"
        : "+f"(d[0]), "+f"(d[1]), "+f"(d[2]), "+f"(d[3])
        : "r"(a[0]), "r"(a[1]), "r"(a[2]), "r"(a[3]), "r"(b[0]), "r"(b[1]));
}

// ---------------- weight transpose + tf32 pre-round ----------------
__global__ void k_transpose(const float* __restrict__ wf,
                            const float* __restrict__ wg,
                            const float* __restrict__ ws) {
    int idx = blockIdx.x * 256 + threadIdx.x;
    if (idx >= 3 * CC * KTOT) return;
    int conv = idx / (CC * KTOT);
    int r    = idx % (CC * KTOT);
    int co   = r >> 8;
    int k    = r & 255;
    int tap  = k >> 7;
    int cin  = k & 127;
    const float* src = (conv == 0) ? wf : ((conv == 1) ? wg : ws);
    g_wtA[idx] = rtf32(src[(co * CC + cin) * 2 + tap]);
}

// ---------------- kernel 1: f/g convs + gated activation ----------------
__global__ __launch_bounds__(256, 2) void k_fg(const float* __restrict__ x) {
    extern __shared__ float sm[];
    float* wsf = sm;                     // [128][MSTR]
    float* wsg = sm + 128 * MSTR;        // [128][MSTR]
    float* bs  = wsg + 128 * MSTR;       // [32][BSTR]

    const int tid  = threadIdx.x;
    const int wid  = tid >> 5;
    const int lane = tid & 31;
    const int grp  = lane >> 2;          // 0..7
    const int qc   = lane & 3;           // 0..3
    const int wm   = wid & 3;            // warp M tile (32 couts)
    const int wn   = wid >> 2;           // warp N tile (32 t)
    const int b     = blockIdx.y;
    const int tbase = blockIdx.x * NT;
    const float* xb = x + (size_t)b * CC * TLEN;

    float accf[2][4][4], accg[2][4][4];
#pragma unroll
    for (int mi = 0; mi < 2; mi++)
#pragma unroll
        for (int ni = 0; ni < 4; ni++)
#pragma unroll
            for (int i = 0; i < 4; i++) { accf[mi][ni][i] = 0.f; accg[mi][ni][i] = 0.f; }

    for (int c = 0; c < NCHUNK; c++) {
        __syncthreads();
        // stage W chunk [128 co][32 k] for f and g (k-slice c*32..c*32+31)
        {
            const float* gf = g_wtA + c * 32;
            const float* gg = g_wtA + (size_t)CC * KTOT + c * 32;
#pragma unroll
            for (int it = 0; it < 4; it++) {
                int idx = tid + it * 256;           // 0..1023 float4 units
                int row = idx >> 3, j = idx & 7;
                float4 vf = *(const float4*)(gf + (size_t)row * KTOT + j * 4);
                float4 vg = *(const float4*)(gg + (size_t)row * KTOT + j * 4);
                float* df = wsf + row * MSTR + j * 4;
                df[0] = vf.x; df[1] = vf.y; df[2] = vf.z; df[3] = vf.w;
                float* dg = wsg + row * MSTR + j * 4;
                dg[0] = vg.x; dg[1] = vg.y; dg[2] = vg.z; dg[3] = vg.w;
            }
        }
        // stage B chunk [32 k-rows][64 n], dilation shift folded in, tf32-rounded
        {
            const int tap   = c >> 2;
            const int cing  = (c & 3) * 32;
            const int shift = tap ? 0 : -2;   // even -> float2 loads stay aligned
#pragma unroll
            for (int it = 0; it < 4; it++) {
                int idx = tid + it * 256;           // 0..1023 float2 units
                int row = idx >> 5, j = idx & 31;
                int t = tbase + 2 * j + shift;
                const float* xr = xb + (size_t)(cing + row) * TLEN;
                float2 v = make_float2(0.f, 0.f);
                if (t >= 0) v = *(const float2*)(xr + t);
                float* d = bs + row * BSTR + 2 * j;
                d[0] = __uint_as_float(tf32u(v.x));
                d[1] = __uint_as_float(tf32u(v.y));
            }
        }
        __syncthreads();

        // compute: 4 k-fragments of 8
        const uint32_t* apf = (const uint32_t*)wsf;
        const uint32_t* apg = (const uint32_t*)wsg;
        const uint32_t* bp  = (const uint32_t*)bs;
#pragma unroll
        for (int kf = 0; kf < 4; kf++) {
            uint32_t bfr[4][2];
#pragma unroll
            for (int ni = 0; ni < 4; ni++) {
                int col = wn * 32 + ni * 8 + grp;
                bfr[ni][0] = bp[(kf * 8 + qc) * BSTR + col];
                bfr[ni][1] = bp[(kf * 8 + qc + 4) * BSTR + col];
            }
#pragma unroll
            for (int mi = 0; mi < 2; mi++) {
                int r0 = wm * 32 + mi * 16 + grp;
                int kc = kf * 8 + qc;
                uint32_t af[4], ag[4];
                af[0] = apf[r0 * MSTR + kc];       af[1] = apf[(r0 + 8) * MSTR + kc];
                af[2] = apf[r0 * MSTR + kc + 4];   af[3] = apf[(r0 + 8) * MSTR + kc + 4];
                ag[0] = apg[r0 * MSTR + kc];       ag[1] = apg[(r0 + 8) * MSTR + kc];
                ag[2] = apg[r0 * MSTR + kc + 4];   ag[3] = apg[(r0 + 8) * MSTR + kc + 4];
#pragma unroll
                for (int ni = 0; ni < 4; ni++) {
                    mma_tf32(accf[mi][ni], af, bfr[ni]);
                    mma_tf32(accg[mi][ni], ag, bfr[ni]);
                }
            }
        }
    }

    __syncthreads();
    // epilogue: o = tanh(f)*sigmoid(g); smem transpose -> coalesced store
    {
        float* tile = sm + wid * (32 * 33);
        float* ob = g_o + (size_t)b * CC * TLEN;
#pragma unroll
        for (int mi = 0; mi < 2; mi++)
#pragma unroll
            for (int ni = 0; ni < 4; ni++) {
                int r0 = mi * 16 + grp;
                int cb = ni * 8 + qc * 2;
#pragma unroll
                for (int h = 0; h < 2; h++) {      // h=0 -> c0/c1, h=1 -> c2/c3
                    float f0 = accf[mi][ni][h * 2],     g0 = accg[mi][ni][h * 2];
                    float f1 = accf[mi][ni][h * 2 + 1], g1 = accg[mi][ni][h * 2 + 1];
                    float o0 = rtf32(tanhf(f0) * (1.f / (1.f + __expf(-g0))));
                    float o1 = rtf32(tanhf(f1) * (1.f / (1.f + __expf(-g1))));
                    tile[(r0 + h * 8) * 33 + cb]     = o0;
                    tile[(r0 + h * 8) * 33 + cb + 1] = o1;
                }
            }
        __syncwarp();
        int t = tbase + wn * 32 + lane;
#pragma unroll
        for (int j = 0; j < 32; j++)
            ob[(size_t)(wm * 32 + j) * TLEN + t] = tile[j * 33 + lane];
    }
}

// ---------------- kernel 2: skip conv + residual ----------------
__global__ __launch_bounds__(256, 2) void k_skip(const float* __restrict__ x,
                                                 float* __restrict__ out,
                                                 float* __restrict__ skip) {
    extern __shared__ float sm[];
    float* wss = sm;                     // [128][MSTR]
    float* bs  = sm + 128 * MSTR;        // [32][BSTR]

    const int tid  = threadIdx.x;
    const int wid  = tid >> 5;
    const int lane = tid & 31;
    const int grp  = lane >> 2;
    const int qc   = lane & 3;
    const int wm   = wid & 3;
    const int wn   = wid >> 2;
    const int b     = blockIdx.y;
    const int tbase = blockIdx.x * NT;
    const float* obase = g_o + (size_t)b * CC * TLEN;

    float acc[2][4][4];
#pragma unroll
    for (int mi = 0; mi < 2; mi++)
#pragma unroll
        for (int ni = 0; ni < 4; ni++)
#pragma unroll
            for (int i = 0; i < 4; i++) acc[mi][ni][i] = 0.f;

    for (int c = 0; c < NCHUNK; c++) {
        __syncthreads();
        {
            const float* gs = g_wtA + (size_t)2 * CC * KTOT + c * 32;
#pragma unroll
            for (int it = 0; it < 4; it++) {
                int idx = tid + it * 256;
                int row = idx >> 3, j = idx & 7;
                float4 vs = *(const float4*)(gs + (size_t)row * KTOT + j * 4);
                float* ds = wss + row * MSTR + j * 4;
                ds[0] = vs.x; ds[1] = vs.y; ds[2] = vs.z; ds[3] = vs.w;
            }
        }
        {
            const int tap  = c >> 2;
            const int cing = (c & 3) * 32;
#pragma unroll
            for (int it = 0; it < 4; it++) {
                int idx = tid + it * 256;
                int row = idx >> 5, j = idx & 31;
                const float* xr = obase + (size_t)(cing + row) * TLEN;
                float2 v;
                if (tap) {
                    int t = tbase + 2 * j;
                    v = *(const float2*)(xr + t);
                } else {
                    int t = tbase + 2 * j - 1;   // odd -> scalar loads
                    v.x = (t >= 0) ? xr[t] : 0.f;
                    v.y = xr[t + 1];
                }
                float* d = bs + row * BSTR + 2 * j;
                d[0] = v.x; d[1] = v.y;          // g_o already tf32-rounded
            }
        }
        __syncthreads();

        const uint32_t* ap = (const uint32_t*)wss;
        const uint32_t* bp = (const uint32_t*)bs;
#pragma unroll
        for (int kf = 0; kf < 4; kf++) {
            uint32_t bfr[4][2];
#pragma unroll
            for (int ni = 0; ni < 4; ni++) {
                int col = wn * 32 + ni * 8 + grp;
                bfr[ni][0] = bp[(kf * 8 + qc) * BSTR + col];
                bfr[ni][1] = bp[(kf * 8 + qc + 4) * BSTR + col];
            }
#pragma unroll
            for (int mi = 0; mi < 2; mi++) {
                int r0 = wm * 32 + mi * 16 + grp;
                int kc = kf * 8 + qc;
                uint32_t a[4];
                a[0] = ap[r0 * MSTR + kc];       a[1] = ap[(r0 + 8) * MSTR + kc];
                a[2] = ap[r0 * MSTR + kc + 4];   a[3] = ap[(r0 + 8) * MSTR + kc + 4];
#pragma unroll
                for (int ni = 0; ni < 4; ni++)
                    mma_tf32(acc[mi][ni], a, bfr[ni]);
            }
        }
    }

    __syncthreads();
    // epilogue: skip = D; out = D + x (full fp32 outputs)
    {
        float* tile = sm + wid * (32 * 33);
        const float* xb  = x    + (size_t)b * CC * TLEN;
        float* outb      = out  + (size_t)b * CC * TLEN;
        float* skipb     = skip + (size_t)b * CC * TLEN;
#pragma unroll
        for (int mi = 0; mi < 2; mi++)
#pragma unroll
            for (int ni = 0; ni < 4; ni++) {
                int r0 = mi * 16 + grp;
                int cb = ni * 8 + qc * 2;
                tile[r0 * 33 + cb]           = acc[mi][ni][0];
                tile[r0 * 33 + cb + 1]       = acc[mi][ni][1];
                tile[(r0 + 8) * 33 + cb]     = acc[mi][ni][2];
                tile[(r0 + 8) * 33 + cb + 1] = acc[mi][ni][3];
            }
        __syncwarp();
        int t = tbase + wn * 32 + lane;
#pragma unroll
        for (int j = 0; j < 32; j++) {
            size_t off = (size_t)(wm * 32 + j) * TLEN + t;
            float sv = tile[j * 33 + lane];
            skipb[off] = sv;
            outb[off]  = sv + xb[off];
        }
    }
}

extern "C" void kernel_launch(void* const* d_in, const int* in_sizes, int n_in,
                              void* d_out, int out_size) {
    const float* x  = (const float*)d_in[0];
    const float* wf = (const float*)d_in[1];
    const float* wg = (const float*)d_in[2];
    const float* ws = (const float*)d_in[3];

    float* out  = (float*)d_out;
    float* skip = out + (size_t)BB * CC * TLEN;

    cudaFuncSetAttribute(k_fg,   cudaFuncAttributeMaxDynamicSharedMemorySize, SMEM1);
    cudaFuncSetAttribute(k_skip, cudaFuncAttributeMaxDynamicSharedMemorySize, SMEM2);

    k_transpose<<<(3 * CC * KTOT + 255) / 256, 256>>>(wf, wg, ws);

    dim3 grid(TLEN / NT, BB);
    k_fg<<<grid, 256, SMEM1>>>(x);
    k_skip<<<grid, 256, SMEM2>>>(x, out, skip);
}

// round 6
// speedup vs baseline: 3.1696x; 1.8738x over previous
#include <cuda_runtime.h>
#include <cstdint>

#define BB 32
#define CC 128
#define TLEN 16000
#define NT 64
#define KTOT 256

// B smem pair layout: addr(fl2) = kf*1100 + n*17 + qc*4  (conflict-free LDS.64/STS.64)
#define KFSTR 1100
#define SMEMB (8 * KFSTR * 8)   // 8800 fl2 = 70400 bytes (epilogue tiles reuse: 33792 B)

__device__ float g_wtA[3 * CC * KTOT];        // fragment-ordered tf32 weights (float4 units)
__device__ float g_o[(size_t)BB * CC * TLEN]; // gated output, tf32-rounded

// ---------------- helpers ----------------
__device__ __forceinline__ uint32_t tf32u(float x) {
    uint32_t u; asm("cvt.rna.tf32.f32 %0, %1;" : "=r"(u) : "f"(x)); return u;
}
__device__ __forceinline__ float rtf32(float x) { return __uint_as_float(tf32u(x)); }

__device__ __forceinline__ void mma_tf32(float* d, const uint32_t* a, const uint32_t* b) {
    asm volatile(
        "mma.sync.aligned.m16n8k8.row.col.f32.tf32.tf32.f32 "
        "{%0,%1,%2,%3}, {%4,%5,%6,%7}, {%8,%9}, {%0,%1,%2,%3};"
        : "+f"(d[0]), "+f"(d[1]), "+f"(d[2]), "+f"(d[3])
        : "r"(a[0]), "r"(a[1]), "r"(a[2]), "r"(a[3]), "r"(b[0]), "r"(b[1]));
}

// ---------------- weight fragment pre-pack (tf32-rounded) ----------------
// Layout: idx = ((((conv*4 + c)*8 + kf)*2 + mi)*4 + wm)*32 + lane, one float4 each.
// float4 = {W[r0][k], W[r0+8][k], W[r0][k+4], W[r0+8][k+4]},
//   r0 = wm*32 + mi*16 + grp, k -> tap = kf>>2, cin = c*32 + (kf&3)*8 + qc.
__global__ void k_transpose(const float* __restrict__ wf,
                            const float* __restrict__ wg,
                            const float* __restrict__ ws) {
    int idx = blockIdx.x * 256 + threadIdx.x;
    if (idx >= 3 * 8192) return;
    int lane = idx & 31;
    int wm   = (idx >> 5) & 3;
    int mi   = (idx >> 7) & 1;
    int kf   = (idx >> 8) & 7;
    int c    = (idx >> 11) & 3;
    int conv = idx >> 13;
    int grp = lane >> 2, qc = lane & 3;
    int r0  = wm * 32 + mi * 16 + grp;
    int cin = c * 32 + (kf & 3) * 8 + qc;
    int tap = kf >> 2;
    const float* src = (conv == 0) ? wf : ((conv == 1) ? wg : ws);
    float4 v;
    v.x = rtf32(src[(r0 * CC + cin) * 2 + tap]);
    v.y = rtf32(src[((r0 + 8) * CC + cin) * 2 + tap]);
    v.z = rtf32(src[(r0 * CC + cin + 4) * 2 + tap]);
    v.w = rtf32(src[((r0 + 8) * CC + cin + 4) * 2 + tap]);
    ((float4*)g_wtA)[idx] = v;
}

// ---------------- kernel 1: f/g convs + gated activation ----------------
__global__ __launch_bounds__(256, 2) void k_fg(const float* __restrict__ x) {
    extern __shared__ float sm[];
    float2* bs2 = (float2*)sm;

    const int tid  = threadIdx.x;
    const int wid  = tid >> 5;
    const int lane = tid & 31;
    const int grp  = lane >> 2;
    const int qc   = lane & 3;
    const int wm   = wid & 3;
    const int wn   = wid >> 2;
    const int b     = blockIdx.y;
    const int tbase = blockIdx.x * NT;
    const float* xb = x + (size_t)b * CC * TLEN;
    const float4* gw4 = (const float4*)g_wtA;

    float accf[2][4][4], accg[2][4][4];
#pragma unroll
    for (int mi = 0; mi < 2; mi++)
#pragma unroll
        for (int ni = 0; ni < 4; ni++)
#pragma unroll
            for (int i = 0; i < 4; i++) { accf[mi][ni][i] = 0.f; accg[mi][ni][i] = 0.f; }

    for (int c = 0; c < 4; c++) {
        __syncthreads();
        // stage B: both taps of 32-cin group, pair layout {cin, cin+4}
#pragma unroll
        for (int it = 0; it < 8; it++) {
            int idx = it * 256 + tid;        // (kf,qc,n)
            int n  = idx & 63;
            int pq = idx >> 6;
            int kf = pq >> 2, q = pq & 3;
            int tap = kf >> 2;
            int cl  = c * 32 + (kf & 3) * 8 + q;
            int t = tbase + n - (tap ? 0 : 2);
            float lo = 0.f, hi = 0.f;
            if (t >= 0) {
                lo = xb[(size_t)cl * TLEN + t];
                hi = xb[(size_t)(cl + 4) * TLEN + t];
            }
            float2 v;
            v.x = __uint_as_float(tf32u(lo));
            v.y = __uint_as_float(tf32u(hi));
            bs2[kf * KFSTR + n * 17 + q * 4] = v;
        }
        __syncthreads();

#pragma unroll
        for (int kf = 0; kf < 8; kf++) {
            uint32_t bfr[4][2];
#pragma unroll
            for (int ni = 0; ni < 4; ni++) {
                float2 v = bs2[kf * KFSTR + (wn * 32 + ni * 8 + grp) * 17 + qc * 4];
                bfr[ni][0] = __float_as_uint(v.x);
                bfr[ni][1] = __float_as_uint(v.y);
            }
#pragma unroll
            for (int mi = 0; mi < 2; mi++) {
                float4 af = gw4[((((0 * 4 + c) * 8 + kf) * 2 + mi) * 4 + wm) * 32 + lane];
                float4 ag = gw4[((((1 * 4 + c) * 8 + kf) * 2 + mi) * 4 + wm) * 32 + lane];
#pragma unroll
                for (int ni = 0; ni < 4; ni++) {
                    mma_tf32(accf[mi][ni], (const uint32_t*)&af, bfr[ni]);
                    mma_tf32(accg[mi][ni], (const uint32_t*)&ag, bfr[ni]);
                }
            }
        }
    }

    __syncthreads();
    // epilogue: o = tanh(f)*sigmoid(g); smem transpose -> coalesced store
    {
        float* tile = sm + wid * (32 * 33);
        float* ob = g_o + (size_t)b * CC * TLEN;
#pragma unroll
        for (int mi = 0; mi < 2; mi++)
#pragma unroll
            for (int ni = 0; ni < 4; ni++) {
                int r0 = mi * 16 + grp;
                int cb = ni * 8 + qc * 2;
#pragma unroll
                for (int h = 0; h < 2; h++) {
                    float f0 = accf[mi][ni][h * 2],     g0 = accg[mi][ni][h * 2];
                    float f1 = accf[mi][ni][h * 2 + 1], g1 = accg[mi][ni][h * 2 + 1];
                    float o0 = rtf32(tanhf(f0) * (1.f / (1.f + __expf(-g0))));
                    float o1 = rtf32(tanhf(f1) * (1.f / (1.f + __expf(-g1))));
                    tile[(r0 + h * 8) * 33 + cb]     = o0;
                    tile[(r0 + h * 8) * 33 + cb + 1] = o1;
                }
            }
        __syncwarp();
        int t = tbase + wn * 32 + lane;
#pragma unroll
        for (int j = 0; j < 32; j++)
            ob[(size_t)(wm * 32 + j) * TLEN + t] = tile[j * 33 + lane];
    }
}

// ---------------- kernel 2: skip conv + residual ----------------
__global__ __launch_bounds__(256, 2) void k_skip(const float* __restrict__ x,
                                                 float* __restrict__ out,
                                                 float* __restrict__ skip) {
    extern __shared__ float sm[];
    float2* bs2 = (float2*)sm;

    const int tid  = threadIdx.x;
    const int wid  = tid >> 5;
    const int lane = tid & 31;
    const int grp  = lane >> 2;
    const int qc   = lane & 3;
    const int wm   = wid & 3;
    const int wn   = wid >> 2;
    const int b     = blockIdx.y;
    const int tbase = blockIdx.x * NT;
    const float* obase = g_o + (size_t)b * CC * TLEN;
    const float4* gw4 = (const float4*)g_wtA;

    float acc[2][4][4];
#pragma unroll
    for (int mi = 0; mi < 2; mi++)
#pragma unroll
        for (int ni = 0; ni < 4; ni++)
#pragma unroll
            for (int i = 0; i < 4; i++) acc[mi][ni][i] = 0.f;

    for (int c = 0; c < 4; c++) {
        __syncthreads();
        // stage B from o: both taps (t-1, t), pair layout {co, co+4}
#pragma unroll
        for (int it = 0; it < 8; it++) {
            int idx = it * 256 + tid;
            int n  = idx & 63;
            int pq = idx >> 6;
            int kf = pq >> 2, q = pq & 3;
            int tap = kf >> 2;
            int cl  = c * 32 + (kf & 3) * 8 + q;
            int t = tbase + n - (tap ? 0 : 1);
            float lo = 0.f, hi = 0.f;
            if (t >= 0) {
                lo = obase[(size_t)cl * TLEN + t];
                hi = obase[(size_t)(cl + 4) * TLEN + t];
            }
            float2 v; v.x = lo; v.y = hi;    // g_o already tf32-rounded
            bs2[kf * KFSTR + n * 17 + q * 4] = v;
        }
        __syncthreads();

#pragma unroll
        for (int kf = 0; kf < 8; kf++) {
            uint32_t bfr[4][2];
#pragma unroll
            for (int ni = 0; ni < 4; ni++) {
                float2 v = bs2[kf * KFSTR + (wn * 32 + ni * 8 + grp) * 17 + qc * 4];
                bfr[ni][0] = __float_as_uint(v.x);
                bfr[ni][1] = __float_as_uint(v.y);
            }
#pragma unroll
            for (int mi = 0; mi < 2; mi++) {
                float4 a4 = gw4[((((2 * 4 + c) * 8 + kf) * 2 + mi) * 4 + wm) * 32 + lane];
#pragma unroll
                for (int ni = 0; ni < 4; ni++)
                    mma_tf32(acc[mi][ni], (const uint32_t*)&a4, bfr[ni]);
            }
        }
    }

    __syncthreads();
    // epilogue: skip = D; out = D + x
    {
        float* tile = sm + wid * (32 * 33);
        const float* xb = x + (size_t)b * CC * TLEN;
        float* outb  = out  + (size_t)b * CC * TLEN;
        float* skipb = skip + (size_t)b * CC * TLEN;
#pragma unroll
        for (int mi = 0; mi < 2; mi++)
#pragma unroll
            for (int ni = 0; ni < 4; ni++) {
                int r0 = mi * 16 + grp;
                int cb = ni * 8 + qc * 2;
                tile[r0 * 33 + cb]           = acc[mi][ni][0];
                tile[r0 * 33 + cb + 1]       = acc[mi][ni][1];
                tile[(r0 + 8) * 33 + cb]     = acc[mi][ni][2];
                tile[(r0 + 8) * 33 + cb + 1] = acc[mi][ni][3];
            }
        __syncwarp();
        int t = tbase + wn * 32 + lane;
#pragma unroll
        for (int j = 0; j < 32; j++) {
            size_t off = (size_t)(wm * 32 + j) * TLEN + t;
            float sv = tile[j * 33 + lane];
            skipb[off] = sv;
            outb[off]  = sv + xb[off];
        }
    }
}

extern "C" void kernel_launch(void* const* d_in, const int* in_sizes, int n_in,
                              void* d_out, int out_size) {
    const float* x  = (const float*)d_in[0];
    const float* wf = (const float*)d_in[1];
    const float* wg = (const float*)d_in[2];
    const float* ws = (const float*)d_in[3];

    float* out  = (float*)d_out;
    float* skip = out + (size_t)BB * CC * TLEN;

    cudaFuncSetAttribute(k_fg,   cudaFuncAttributeMaxDynamicSharedMemorySize, SMEMB);
    cudaFuncSetAttribute(k_skip, cudaFuncAttributeMaxDynamicSharedMemorySize, SMEMB);

    k_transpose<<<(3 * 8192 + 255) / 256, 256>>>(wf, wg, ws);

    dim3 grid(TLEN / NT, BB);
    k_fg<<<grid, 256, SMEMB>>>(x);
    k_skip<<<grid, 256, SMEMB>>>(x, out, skip);
}

// round 9
// speedup vs baseline: 4.2780x; 1.3497x over previous
#include <cuda_runtime.h>
#include <cuda_fp16.h>
#include <cstdint>

#define BB 32
#define CC 128
#define TLEN 16000
#define NT 64

// B smem pair layout: uint2 addr = kf*1100 + n*17 + qc*4  (conflict-free)
#define KFSTR 1100
#define SMEMB (4 * KFSTR * 8)   // 4400 uint2 = 35200 B (epilogue tiles need 33792 B)

__device__ uint4  g_wtA[3 * 4096];             // fp16 fragment-packed weights
__device__ __half g_o[(size_t)BB * CC * TLEN]; // gated output, fp16

// ---------------- helpers ----------------
__device__ __forceinline__ uint32_t h2pack(float lo, float hi) {
    __half2 h = __floats2half2_rn(lo, hi);
    return *(uint32_t*)&h;
}

__device__ __forceinline__ void mma_f16(float* d, const uint32_t* a, const uint32_t* b) {
    asm volatile(
        "mma.sync.aligned.m16n8k16.row.col.f32.f16.f16.f32 "
        "{%0,%1,%2,%3}, {%4,%5,%6,%7}, {%8,%9}, {%0,%1,%2,%3};"
        : "+f"(d[0]), "+f"(d[1]), "+f"(d[2]), "+f"(d[3])
        : "r"(a[0]), "r"(a[1]), "r"(a[2]), "r"(a[3]), "r"(b[0]), "r"(b[1]));
}

// ---------------- weight fragment pre-pack (fp16) ----------------
// uint4 idx = conv*4096 + c*1024 + kf*256 + mi*128 + wm*32 + lane
// tap = kf>>1, cb = c*32 + (kf&1)*16 + qc*2, r0 = wm*32 + mi*16 + grp
// x = {W[r0][cb],W[r0][cb+1]}  y = {W[r0+8][cb],W[r0+8][cb+1]}
// z = {W[r0][cb+8],W[r0][cb+9]} w = {W[r0+8][cb+8],W[r0+8][cb+9]}
__global__ void k_transpose(const float* __restrict__ wf,
                            const float* __restrict__ wg,
                            const float* __restrict__ ws) {
    int idx = blockIdx.x * 256 + threadIdx.x;
    if (idx >= 3 * 4096) return;
    int lane = idx & 31;
    int wm   = (idx >> 5) & 3;
    int mi   = (idx >> 7) & 1;
    int kf   = (idx >> 8) & 3;
    int c    = (idx >> 10) & 3;
    int conv = idx >> 12;
    int grp = lane >> 2, qc = lane & 3;
    int r0  = wm * 32 + mi * 16 + grp;
    int cb  = c * 32 + (kf & 1) * 16 + qc * 2;
    int tap = kf >> 1;
    const float* src = (conv == 0) ? wf : ((conv == 1) ? wg : ws);
#define WV(r, ci) src[((r) * CC + (ci)) * 2 + tap]
    uint4 v;
    v.x = h2pack(WV(r0, cb),     WV(r0, cb + 1));
    v.y = h2pack(WV(r0 + 8, cb), WV(r0 + 8, cb + 1));
    v.z = h2pack(WV(r0, cb + 8),     WV(r0, cb + 9));
    v.w = h2pack(WV(r0 + 8, cb + 8), WV(r0 + 8, cb + 9));
#undef WV
    g_wtA[idx] = v;
}

// ---------------- kernel 1: f/g convs + gated activation ----------------
__global__ __launch_bounds__(256, 2) void k_fg(const float* __restrict__ x) {
    extern __shared__ float sm[];
    uint2* bsu = (uint2*)sm;

    const int tid  = threadIdx.x;
    const int wid  = tid >> 5;
    const int lane = tid & 31;
    const int grp  = lane >> 2;
    const int qc   = lane & 3;
    const int wm   = wid & 3;
    const int wn   = wid >> 2;
    const int b     = blockIdx.y;
    const int tbase = blockIdx.x * NT;
    const float* xb = x + (size_t)b * CC * TLEN;

    float accf[2][4][4], accg[2][4][4];
#pragma unroll
    for (int mi = 0; mi < 2; mi++)
#pragma unroll
        for (int ni = 0; ni < 4; ni++)
#pragma unroll
            for (int i = 0; i < 4; i++) { accf[mi][ni][i] = 0.f; accg[mi][ni][i] = 0.f; }

    for (int c = 0; c < 4; c++) {
        __syncthreads();
        // stage B: 32-cin group, both taps, fp16 pair layout
#pragma unroll
        for (int it = 0; it < 4; it++) {
            int idx = it * 256 + tid;        // (kf, q, n): 1024 uint2
            int n  = idx & 63;
            int pq = idx >> 6;
            int kf = pq >> 2, q = pq & 3;
            int tap = kf >> 1;
            int cb  = c * 32 + (kf & 1) * 16 + q * 2;
            int t = tbase + n - (tap ? 0 : 2);
            float l0 = 0.f, l1 = 0.f, h0 = 0.f, h1 = 0.f;
            if (t >= 0) {
                const float* xp = xb + t;
                l0 = xp[(size_t)cb * TLEN];
                l1 = xp[(size_t)(cb + 1) * TLEN];
                h0 = xp[(size_t)(cb + 8) * TLEN];
                h1 = xp[(size_t)(cb + 9) * TLEN];
            }
            uint2 v;
            v.x = h2pack(l0, l1);
            v.y = h2pack(h0, h1);
            bsu[kf * KFSTR + n * 17 + q * 4] = v;
        }
        __syncthreads();

#pragma unroll
        for (int kf = 0; kf < 4; kf++) {
            uint32_t bfr[4][2];
#pragma unroll
            for (int ni = 0; ni < 4; ni++) {
                uint2 v = bsu[kf * KFSTR + (wn * 32 + ni * 8 + grp) * 17 + qc * 4];
                bfr[ni][0] = v.x;
                bfr[ni][1] = v.y;
            }
#pragma unroll
            for (int mi = 0; mi < 2; mi++) {
                uint4 af = g_wtA[0 * 4096 + c * 1024 + kf * 256 + mi * 128 + wm * 32 + lane];
                uint4 ag = g_wtA[1 * 4096 + c * 1024 + kf * 256 + mi * 128 + wm * 32 + lane];
#pragma unroll
                for (int ni = 0; ni < 4; ni++) {
                    mma_f16(accf[mi][ni], (const uint32_t*)&af, bfr[ni]);
                    mma_f16(accg[mi][ni], (const uint32_t*)&ag, bfr[ni]);
                }
            }
        }
    }

    __syncthreads();
    // epilogue: o = tanh(f)*sigmoid(g); smem transpose -> coalesced fp16 store
    {
        float* tile = sm + wid * (32 * 33);
        __half* ob = g_o + (size_t)b * CC * TLEN;
#pragma unroll
        for (int mi = 0; mi < 2; mi++)
#pragma unroll
            for (int ni = 0; ni < 4; ni++) {
                int r0 = mi * 16 + grp;
                int cb = ni * 8 + qc * 2;
#pragma unroll
                for (int h = 0; h < 2; h++) {
                    float f0 = accf[mi][ni][h * 2],     g0 = accg[mi][ni][h * 2];
                    float f1 = accf[mi][ni][h * 2 + 1], g1 = accg[mi][ni][h * 2 + 1];
                    tile[(r0 + h * 8) * 33 + cb]     = tanhf(f0) * (1.f / (1.f + __expf(-g0)));
                    tile[(r0 + h * 8) * 33 + cb + 1] = tanhf(f1) * (1.f / (1.f + __expf(-g1)));
                }
            }
        __syncwarp();
        int t = tbase + wn * 32 + lane;
#pragma unroll
        for (int j = 0; j < 32; j++)
            ob[(size_t)(wm * 32 + j) * TLEN + t] = __float2half_rn(tile[j * 33 + lane]);
    }
}

// ---------------- kernel 2: skip conv + residual ----------------
__global__ __launch_bounds__(256, 2) void k_skip(const float* __restrict__ x,
                                                 float* __restrict__ out,
                                                 float* __restrict__ skip) {
    extern __shared__ float sm[];
    uint2* bsu = (uint2*)sm;

    const int tid  = threadIdx.x;
    const int wid  = tid >> 5;
    const int lane = tid & 31;
    const int grp  = lane >> 2;
    const int qc   = lane & 3;
    const int wm   = wid & 3;
    const int wn   = wid >> 2;
    const int b     = blockIdx.y;
    const int tbase = blockIdx.x * NT;
    const __half* obase = g_o + (size_t)b * CC * TLEN;

    float acc[2][4][4];
#pragma unroll
    for (int mi = 0; mi < 2; mi++)
#pragma unroll
        for (int ni = 0; ni < 4; ni++)
#pragma unroll
            for (int i = 0; i < 4; i++) acc[mi][ni][i] = 0.f;

    for (int c = 0; c < 4; c++) {
        __syncthreads();
#pragma unroll
        for (int it = 0; it < 4; it++) {
            int idx = it * 256 + tid;
            int n  = idx & 63;
            int pq = idx >> 6;
            int kf = pq >> 2, q = pq & 3;
            int tap = kf >> 1;
            int cb  = c * 32 + (kf & 1) * 16 + q * 2;
            int t = tbase + n - (tap ? 0 : 1);
            __half z = __float2half(0.f);
            __half l0 = z, l1 = z, h0 = z, h1 = z;
            if (t >= 0) {
                const __half* op = obase + t;
                l0 = op[(size_t)cb * TLEN];
                l1 = op[(size_t)(cb + 1) * TLEN];
                h0 = op[(size_t)(cb + 8) * TLEN];
                h1 = op[(size_t)(cb + 9) * TLEN];
            }
            uint2 v;
            __half2 vlo = __halves2half2(l0, l1);
            __half2 vhi = __halves2half2(h0, h1);
            v.x = *(uint32_t*)&vlo;
            v.y = *(uint32_t*)&vhi;
            bsu[kf * KFSTR + n * 17 + q * 4] = v;
        }
        __syncthreads();

#pragma unroll
        for (int kf = 0; kf < 4; kf++) {
            uint32_t bfr[4][2];
#pragma unroll
            for (int ni = 0; ni < 4; ni++) {
                uint2 v = bsu[kf * KFSTR + (wn * 32 + ni * 8 + grp) * 17 + qc * 4];
                bfr[ni][0] = v.x;
                bfr[ni][1] = v.y;
            }
#pragma unroll
            for (int mi = 0; mi < 2; mi++) {
                uint4 a4 = g_wtA[2 * 4096 + c * 1024 + kf * 256 + mi * 128 + wm * 32 + lane];
#pragma unroll
                for (int ni = 0; ni < 4; ni++)
                    mma_f16(acc[mi][ni], (const uint32_t*)&a4, bfr[ni]);
            }
        }
    }

    __syncthreads();
    // epilogue: skip = D; out = D + x (fp32 outputs)
    {
        float* tile = sm + wid * (32 * 33);
        const float* xb = x + (size_t)b * CC * TLEN;
        float* outb  = out  + (size_t)b * CC * TLEN;
        float* skipb = skip + (size_t)b * CC * TLEN;
#pragma unroll
        for (int mi = 0; mi < 2; mi++)
#pragma unroll
            for (int ni = 0; ni < 4; ni++) {
                int r0 = mi * 16 + grp;
                int cb = ni * 8 + qc * 2;
                tile[r0 * 33 + cb]           = acc[mi][ni][0];
                tile[r0 * 33 + cb + 1]       = acc[mi][ni][1];
                tile[(r0 + 8) * 33 + cb]     = acc[mi][ni][2];
                tile[(r0 + 8) * 33 + cb + 1] = acc[mi][ni][3];
            }
        __syncwarp();
        int t = tbase + wn * 32 + lane;
#pragma unroll
        for (int j = 0; j < 32; j++) {
            size_t off = (size_t)(wm * 32 + j) * TLEN + t;
            float sv = tile[j * 33 + lane];
            skipb[off] = sv;
            outb[off]  = sv + xb[off];
        }
    }
}

extern "C" void kernel_launch(void* const* d_in, const int* in_sizes, int n_in,
                              void* d_out, int out_size) {
    const float* x  = (const float*)d_in[0];
    const float* wf = (const float*)d_in[1];
    const float* wg = (const float*)d_in[2];
    const float* ws = (const float*)d_in[3];

    float* out  = (float*)d_out;
    float* skip = out + (size_t)BB * CC * TLEN;

    cudaFuncSetAttribute(k_fg,   cudaFuncAttributeMaxDynamicSharedMemorySize, SMEMB);
    cudaFuncSetAttribute(k_skip, cudaFuncAttributeMaxDynamicSharedMemorySize, SMEMB);

    k_transpose<<<(3 * 4096 + 255) / 256, 256>>>(wf, wg, ws);

    dim3 grid(TLEN / NT, BB);
    k_fg<<<grid, 256, SMEMB>>>(x);
    k_skip<<<grid, 256, SMEMB>>>(x, out, skip);
}

// round 10
// speedup vs baseline: 5.1129x; 1.1952x over previous
#include <cuda_runtime.h>
#include <cuda_fp16.h>
#include <cstdint>

#define BB 32
#define CC 128
#define TLEN 16000
#define NTO 63              // valid output columns per block (f/g computes 64, shifted -1)
#define NBLK 254            // ceil(16000/63)

// B smem pair layout: uint2 addr = kf*1100 + n*17 + qc*4  (conflict-free)
#define KFSTR 1100
#define BSU_BYTES (4 * KFSTR * 8)        // 35200 B (also overlays 8 warp transpose tiles: 33792 B)
#define OT_OFF    35328                  // half2 o-tile, t-major [64 j][65 half2]
#define OT_H2     65
#define SMEMF     (OT_OFF + 64 * OT_H2 * 4)   // 51968 B

__device__ uint4 g_wtA[3 * 4096];        // fp16 fragment-packed weights

// ---------------- helpers ----------------
__device__ __forceinline__ uint32_t h2pack(float lo, float hi) {
    __half2 h = __floats2half2_rn(lo, hi);
    return *(uint32_t*)&h;
}

__device__ __forceinline__ void mma_f16(float* d, const uint32_t* a, const uint32_t* b) {
    asm volatile(
        "mma.sync.aligned.m16n8k16.row.col.f32.f16.f16.f32 "
        "{%0,%1,%2,%3}, {%4,%5,%6,%7}, {%8,%9}, {%0,%1,%2,%3};"
        : "+f"(d[0]), "+f"(d[1]), "+f"(d[2]), "+f"(d[3])
        : "r"(a[0]), "r"(a[1]), "r"(a[2]), "r"(a[3]), "r"(b[0]), "r"(b[1]));
}

// ---------------- weight fragment pre-pack (fp16) ----------------
__global__ void k_transpose(const float* __restrict__ wf,
                            const float* __restrict__ wg,
                            const float* __restrict__ ws) {
    int idx = blockIdx.x * 256 + threadIdx.x;
    if (idx >= 3 * 4096) return;
    int lane = idx & 31;
    int wm   = (idx >> 5) & 3;
    int mi   = (idx >> 7) & 1;
    int kf   = (idx >> 8) & 3;
    int c    = (idx >> 10) & 3;
    int conv = idx >> 12;
    int grp = lane >> 2, qc = lane & 3;
    int r0  = wm * 32 + mi * 16 + grp;
    int cb  = c * 32 + (kf & 1) * 16 + qc * 2;
    int tap = kf >> 1;
    const float* src = (conv == 0) ? wf : ((conv == 1) ? wg : ws);
#define WV(r, ci) src[((r) * CC + (ci)) * 2 + tap]
    uint4 v;
    v.x = h2pack(WV(r0, cb),     WV(r0, cb + 1));
    v.y = h2pack(WV(r0 + 8, cb), WV(r0 + 8, cb + 1));
    v.z = h2pack(WV(r0, cb + 8),     WV(r0, cb + 9));
    v.w = h2pack(WV(r0 + 8, cb + 8), WV(r0 + 8, cb + 9));
#undef WV
    g_wtA[idx] = v;
}

// ---------------- fused: f/g convs -> gated act (smem) -> skip conv -> residual ----
__global__ __launch_bounds__(256, 2) void k_fused(const float* __restrict__ x,
                                                  float* __restrict__ out,
                                                  float* __restrict__ skip) {
    extern __shared__ float sm[];
    uint2*     bsu = (uint2*)sm;                       // staging (overlaid by tiles in epilogues)
    uint32_t*  ot  = (uint32_t*)((char*)sm + OT_OFF);  // o-tile, t-major half2

    const int tid  = threadIdx.x;
    const int wid  = tid >> 5;
    const int lane = tid & 31;
    const int grp  = lane >> 2;
    const int qc   = lane & 3;
    const int wm   = wid & 3;
    const int wn   = wid >> 2;
    const int b       = blockIdx.y;
    const int tbase   = blockIdx.x * NTO;   // output base
    const int tfg     = tbase - 1;          // f/g tile: t = tfg + n, n in [0,64)
    const float* xb = x + (size_t)b * CC * TLEN;

    // ================= Phase A: f/g GEMMs =================
    float accf[2][4][4], accg[2][4][4];
#pragma unroll
    for (int mi = 0; mi < 2; mi++)
#pragma unroll
        for (int ni = 0; ni < 4; ni++)
#pragma unroll
            for (int i = 0; i < 4; i++) { accf[mi][ni][i] = 0.f; accg[mi][ni][i] = 0.f; }

    for (int c = 0; c < 4; c++) {
        __syncthreads();
#pragma unroll
        for (int it = 0; it < 4; it++) {
            int idx = it * 256 + tid;
            int n  = idx & 63;
            int pq = idx >> 6;
            int kf = pq >> 2, q = pq & 3;
            int tap = kf >> 1;
            int cb  = c * 32 + (kf & 1) * 16 + q * 2;
            int t = tfg + n - (tap ? 0 : 2);
            float l0 = 0.f, l1 = 0.f, h0 = 0.f, h1 = 0.f;
            if (t >= 0 && t < TLEN) {
                const float* xp = xb + t;
                l0 = xp[(size_t)cb * TLEN];
                l1 = xp[(size_t)(cb + 1) * TLEN];
                h0 = xp[(size_t)(cb + 8) * TLEN];
                h1 = xp[(size_t)(cb + 9) * TLEN];
            }
            uint2 v;
            v.x = h2pack(l0, l1);
            v.y = h2pack(h0, h1);
            bsu[kf * KFSTR + n * 17 + q * 4] = v;
        }
        __syncthreads();

#pragma unroll
        for (int kf = 0; kf < 4; kf++) {
            uint32_t bfr[4][2];
#pragma unroll
            for (int ni = 0; ni < 4; ni++) {
                uint2 v = bsu[kf * KFSTR + (wn * 32 + ni * 8 + grp) * 17 + qc * 4];
                bfr[ni][0] = v.x;
                bfr[ni][1] = v.y;
            }
#pragma unroll
            for (int mi = 0; mi < 2; mi++) {
                uint4 af = g_wtA[0 * 4096 + c * 1024 + kf * 256 + mi * 128 + wm * 32 + lane];
                uint4 ag = g_wtA[1 * 4096 + c * 1024 + kf * 256 + mi * 128 + wm * 32 + lane];
#pragma unroll
                for (int ni = 0; ni < 4; ni++) {
                    mma_f16(accf[mi][ni], (const uint32_t*)&af, bfr[ni]);
                    mma_f16(accg[mi][ni], (const uint32_t*)&ag, bfr[ni]);
                }
            }
        }
    }

    // Phase A epilogue: gated activation -> o-tile in smem (no global traffic)
    __syncthreads();                         // bsu reads done; reuse as transpose tiles
    {
        float* tile = sm + wid * (32 * 33);
#pragma unroll
        for (int mi = 0; mi < 2; mi++)
#pragma unroll
            for (int ni = 0; ni < 4; ni++) {
                int r0 = mi * 16 + grp;
                int cb = ni * 8 + qc * 2;
#pragma unroll
                for (int h = 0; h < 2; h++) {
                    float f0 = accf[mi][ni][h * 2],     g0 = accg[mi][ni][h * 2];
                    float f1 = accf[mi][ni][h * 2 + 1], g1 = accg[mi][ni][h * 2 + 1];
                    float t0 = 1.f - __fdividef(2.f, 1.f + __expf(2.f * f0));
                    float t1 = 1.f - __fdividef(2.f, 1.f + __expf(2.f * f1));
                    float s0 = __fdividef(1.f, 1.f + __expf(-g0));
                    float s1 = __fdividef(1.f, 1.f + __expf(-g1));
                    tile[(r0 + h * 8) * 33 + cb]     = t0 * s0;
                    tile[(r0 + h * 8) * 33 + cb + 1] = t1 * s1;
                }
            }
        __syncwarp();
        // transposed pack: row j = t-local, adjacent couts -> one half2
        int jrow = wn * 32 + lane;
#pragma unroll
        for (int jj = 0; jj < 16; jj++) {
            float lo = tile[(2 * jj) * 33 + lane];
            float hi = tile[(2 * jj + 1) * 33 + lane];
            ot[jrow * OT_H2 + (wm * 32 + 2 * jj) / 2] = h2pack(lo, hi);
        }
    }
    __syncthreads();                         // o-tile complete before phase B staging

    // ================= Phase B: skip GEMM =================
    float acc[2][4][4];
#pragma unroll
    for (int mi = 0; mi < 2; mi++)
#pragma unroll
        for (int ni = 0; ni < 4; ni++)
#pragma unroll
            for (int i = 0; i < 4; i++) acc[mi][ni][i] = 0.f;

    for (int c = 0; c < 4; c++) {
        if (c) __syncthreads();
#pragma unroll
        for (int it = 0; it < 4; it++) {
            int idx = it * 256 + tid;
            int n  = idx & 63;
            int pq = idx >> 6;
            int kf = pq >> 2, q = pq & 3;
            int tap = kf >> 1;
            int cb  = c * 32 + (kf & 1) * 16 + q * 2;
            int j = n + tap; if (j > 63) j = 63;   // n=63 is a masked output
            uint2 v;
            v.x = ot[j * OT_H2 + cb / 2];
            v.y = ot[j * OT_H2 + cb / 2 + 4];
            bsu[kf * KFSTR + n * 17 + q * 4] = v;
        }
        __syncthreads();

#pragma unroll
        for (int kf = 0; kf < 4; kf++) {
            uint32_t bfr[4][2];
#pragma unroll
            for (int ni = 0; ni < 4; ni++) {
                uint2 v = bsu[kf * KFSTR + (wn * 32 + ni * 8 + grp) * 17 + qc * 4];
                bfr[ni][0] = v.x;
                bfr[ni][1] = v.y;
            }
#pragma unroll
            for (int mi = 0; mi < 2; mi++) {
                uint4 a4 = g_wtA[2 * 4096 + c * 1024 + kf * 256 + mi * 128 + wm * 32 + lane];
#pragma unroll
                for (int ni = 0; ni < 4; ni++)
                    mma_f16(acc[mi][ni], (const uint32_t*)&a4, bfr[ni]);
            }
        }
    }

    // Phase B epilogue: skip = D, out = D + x
    __syncthreads();
    {
        float* tile = sm + wid * (32 * 33);
        float* outb  = out  + (size_t)b * CC * TLEN;
        float* skipb = skip + (size_t)b * CC * TLEN;
#pragma unroll
        for (int mi = 0; mi < 2; mi++)
#pragma unroll
            for (int ni = 0; ni < 4; ni++) {
                int r0 = mi * 16 + grp;
                int cb = ni * 8 + qc * 2;
                tile[r0 * 33 + cb]           = acc[mi][ni][0];
                tile[r0 * 33 + cb + 1]       = acc[mi][ni][1];
                tile[(r0 + 8) * 33 + cb]     = acc[mi][ni][2];
                tile[(r0 + 8) * 33 + cb + 1] = acc[mi][ni][3];
            }
        __syncwarp();
        int np = wn * 32 + lane;
        int t  = tbase + np;
        if (np < NTO && t < TLEN) {
            const float* xb2 = x + (size_t)b * CC * TLEN;
#pragma unroll
            for (int j = 0; j < 32; j++) {
                size_t off = (size_t)(wm * 32 + j) * TLEN + t;
                float sv = tile[j * 33 + lane];
                skipb[off] = sv;
                outb[off]  = sv + xb2[off];
            }
        }
    }
}

extern "C" void kernel_launch(void* const* d_in, const int* in_sizes, int n_in,
                              void* d_out, int out_size) {
    const float* x  = (const float*)d_in[0];
    const float* wf = (const float*)d_in[1];
    const float* wg = (const float*)d_in[2];
    const float* ws = (const float*)d_in[3];

    float* out  = (float*)d_out;
    float* skip = out + (size_t)BB * CC * TLEN;

    cudaFuncSetAttribute(k_fused, cudaFuncAttributeMaxDynamicSharedMemorySize, SMEMF);

    k_transpose<<<(3 * 4096 + 255) / 256, 256>>>(wf, wg, ws);

    dim3 grid(NBLK, BB);
    k_fused<<<grid, 256, SMEMF>>>(x, out, skip);
}

// round 12
// speedup vs baseline: 5.4820x; 1.0722x over previous
#include <cuda_runtime.h>
#include <cuda_fp16.h>
#include <cstdint>

#define BB 32
#define CC 128
#define TLEN 16000
#define NTO 62               // valid output columns per block (EVEN -> aligned float2 stores)
#define NBLK 259             // ceil(16000/62)

// smem (u32 units): xt = x tile, t-major half2{cin,cin+1}, stride 68 (banks 4g+q bijective)
//                   ot = o tile, t-major half2{cout,cout+1}, stride 68, 65 rows (row 64 = pad)
#define XTS   68
#define XROWS 68
#define OT_U32_OFF (XROWS * XTS)             // 4624
#define SMEMF ((XROWS * XTS + 65 * XTS) * 4) // 36176 B

__device__ uint4 g_wtA[3 * 4096];            // fp16 fragment-packed weights

// ---------------- helpers ----------------
__device__ __forceinline__ uint32_t h2pack(float lo, float hi) {
    __half2 h = __floats2half2_rn(lo, hi);
    return *(uint32_t*)&h;
}

__device__ __forceinline__ void mma_f16(float* d, const uint32_t* a, const uint32_t* b) {
    asm volatile(
        "mma.sync.aligned.m16n8k16.row.col.f32.f16.f16.f32 "
        "{%0,%1,%2,%3}, {%4,%5,%6,%7}, {%8,%9}, {%0,%1,%2,%3};"
        : "+f"(d[0]), "+f"(d[1]), "+f"(d[2]), "+f"(d[3])
        : "r"(a[0]), "r"(a[1]), "r"(a[2]), "r"(a[3]), "r"(b[0]), "r"(b[1]));
}

// ---------------- weight fragment pre-pack (fp16) ----------------
// uint4 idx = conv*4096 + c*1024 + kf*256 + mi*128 + wm*32 + lane
// tap = kf>>1, cb = c*32 + (kf&1)*16 + qc*2, r0 = wm*32 + mi*16 + grp
__global__ void k_transpose(const float* __restrict__ wf,
                            const float* __restrict__ wg,
                            const float* __restrict__ ws) {
    int idx = blockIdx.x * 256 + threadIdx.x;
    if (idx >= 3 * 4096) return;
    int lane = idx & 31;
    int wm   = (idx >> 5) & 3;
    int mi   = (idx >> 7) & 1;
    int kf   = (idx >> 8) & 3;
    int c    = (idx >> 10) & 3;
    int conv = idx >> 12;
    int grp = lane >> 2, qc = lane & 3;
    int r0  = wm * 32 + mi * 16 + grp;
    int cb  = c * 32 + (kf & 1) * 16 + qc * 2;
    int tap = kf >> 1;
    const float* src = (conv == 0) ? wf : ((conv == 1) ? wg : ws);
#define WV(r, ci) src[((r) * CC + (ci)) * 2 + tap]
    uint4 v;
    v.x = h2pack(WV(r0, cb),     WV(r0, cb + 1));
    v.y = h2pack(WV(r0 + 8, cb), WV(r0 + 8, cb + 1));
    v.z = h2pack(WV(r0, cb + 8),     WV(r0, cb + 9));
    v.w = h2pack(WV(r0 + 8, cb + 8), WV(r0 + 8, cb + 9));
#undef WV
    g_wtA[idx] = v;
}

// ---------------- fused: f/g convs -> gated act (smem) -> skip conv -> residual ----
__global__ __launch_bounds__(256, 2) void k_fused(const float* __restrict__ x,
                                                  float* __restrict__ out,
                                                  float* __restrict__ skip) {
    extern __shared__ uint32_t smu[];
    uint32_t* xt = smu;                  // [68 j][68 stride], j=0 <-> t = tbase-3
    uint32_t* ot = smu + OT_U32_OFF;     // [65 j][68 stride], j   <-> t = tbase-1+j

    const int tid  = threadIdx.x;
    const int wid  = tid >> 5;
    const int lane = tid & 31;
    const int grp  = lane >> 2;
    const int qc   = lane & 3;
    const int wm   = wid & 3;
    const int wn   = wid >> 2;
    const int b     = blockIdx.y;
    const int tbase = blockIdx.x * NTO;  // EVEN
    const float* xb = x + (size_t)b * CC * TLEN;

    // ---- stage x tile once (68 rows x 64 cin-pairs = 4352 = 17*256) ----
#pragma unroll
    for (int it = 0; it < 17; it++) {
        int idx = it * 256 + tid;
        int cp = idx / XROWS;            // 0..63
        int j  = idx - cp * XROWS;       // 0..67 (lane-contiguous -> coalesced LDG)
        int t  = tbase - 3 + j;
        float lo = 0.f, hi = 0.f;
        if (t >= 0 && t < TLEN) {
            lo = xb[(size_t)(2 * cp) * TLEN + t];
            hi = xb[(size_t)(2 * cp + 1) * TLEN + t];
        }
        xt[j * XTS + cp] = h2pack(lo, hi);
    }
    __syncthreads();

    // ================= Phase A: f/g GEMMs (fragments direct from xt) ====
    float accf[2][4][4], accg[2][4][4];
#pragma unroll
    for (int mi = 0; mi < 2; mi++)
#pragma unroll
        for (int ni = 0; ni < 4; ni++)
#pragma unroll
            for (int i = 0; i < 4; i++) { accf[mi][ni][i] = 0.f; accg[mi][ni][i] = 0.f; }

    for (int c = 0; c < 4; c++) {
#pragma unroll
        for (int kf = 0; kf < 4; kf++) {
            const int tap = kf >> 1;
            const int cpb = c * 16 + (kf & 1) * 8;   // half2 base of this kf's cin group
            uint32_t bfr[4][2];
#pragma unroll
            for (int ni = 0; ni < 4; ni++) {
                int j = wn * 32 + ni * 8 + grp + 2 * tap;  // tap0: t-2, tap1: t
                bfr[ni][0] = xt[j * XTS + cpb + qc];
                bfr[ni][1] = xt[j * XTS + cpb + qc + 4];
            }
#pragma unroll
            for (int mi = 0; mi < 2; mi++) {
                uint4 af = g_wtA[0 * 4096 + c * 1024 + kf * 256 + mi * 128 + wm * 32 + lane];
                uint4 ag = g_wtA[1 * 4096 + c * 1024 + kf * 256 + mi * 128 + wm * 32 + lane];
#pragma unroll
                for (int ni = 0; ni < 4; ni++) {
                    mma_f16(accf[mi][ni], (const uint32_t*)&af, bfr[ni]);
                    mma_f16(accg[mi][ni], (const uint32_t*)&ag, bfr[ni]);
                }
            }
        }
    }

    // zero ot pad row 64 (feeds masked columns only; must be finite)
    if (tid < XTS) ot[64 * XTS + tid] = 0;

    // ---- Phase A epilogue: gated act -> ot via shfl pack ----
    {
#pragma unroll
        for (int mi = 0; mi < 2; mi++)
#pragma unroll
            for (int ni = 0; ni < 4; ni++) {
                float f0 = accf[mi][ni][0], f1 = accf[mi][ni][1];
                float f2 = accf[mi][ni][2], f3 = accf[mi][ni][3];
                float g0 = accg[mi][ni][0], g1 = accg[mi][ni][1];
                float g2 = accg[mi][ni][2], g3 = accg[mi][ni][3];
                float v0 = (1.f - __fdividef(2.f, 1.f + __expf(2.f * f0))) * __fdividef(1.f, 1.f + __expf(-g0));
                float v1 = (1.f - __fdividef(2.f, 1.f + __expf(2.f * f1))) * __fdividef(1.f, 1.f + __expf(-g1));
                float v2 = (1.f - __fdividef(2.f, 1.f + __expf(2.f * f2))) * __fdividef(1.f, 1.f + __expf(-g2));
                float v3 = (1.f - __fdividef(2.f, 1.f + __expf(2.f * f3))) * __fdividef(1.f, 1.f + __expf(-g3));
                float u0 = __shfl_xor_sync(0xFFFFFFFF, v0, 4);
                float u1 = __shfl_xor_sync(0xFFFFFFFF, v1, 4);
                float u2 = __shfl_xor_sync(0xFFFFFFFF, v2, 4);
                float u3 = __shfl_xor_sync(0xFFFFFFFF, v3, 4);
                int t0 = wn * 32 + ni * 8 + 2 * qc;
                int cp = wm * 16 + mi * 8 + (grp >> 1);
                if (!(grp & 1)) {          // even grp owns column t0
                    ot[t0 * XTS + cp]     = h2pack(v0, u0);   // rows r0, r0+1
                    ot[t0 * XTS + cp + 4] = h2pack(v2, u2);   // rows r0+8, r0+9
                } else {                   // odd grp owns column t0+1
                    ot[(t0 + 1) * XTS + cp]     = h2pack(u1, v1);
                    ot[(t0 + 1) * XTS + cp + 4] = h2pack(u3, v3);
                }
            }
    }
    __syncthreads();   // ot complete, cross-warp visible

    // ================= Phase B: skip GEMM (fragments direct from ot) =================
    float acc[2][4][4];
#pragma unroll
    for (int mi = 0; mi < 2; mi++)
#pragma unroll
        for (int ni = 0; ni < 4; ni++)
#pragma unroll
            for (int i = 0; i < 4; i++) acc[mi][ni][i] = 0.f;

    for (int c = 0; c < 4; c++) {
#pragma unroll
        for (int kf = 0; kf < 4; kf++) {
            const int tap = kf >> 1;
            const int cpb = c * 16 + (kf & 1) * 8;
            uint32_t bfr[4][2];
#pragma unroll
            for (int ni = 0; ni < 4; ni++) {
                int j = wn * 32 + ni * 8 + grp + tap;     // tap0: o[t-1], tap1: o[t]
                bfr[ni][0] = ot[j * XTS + cpb + qc];
                bfr[ni][1] = ot[j * XTS + cpb + qc + 4];
            }
#pragma unroll
            for (int mi = 0; mi < 2; mi++) {
                uint4 a4 = g_wtA[2 * 4096 + c * 1024 + kf * 256 + mi * 128 + wm * 32 + lane];
#pragma unroll
                for (int ni = 0; ni < 4; ni++)
                    mma_f16(acc[mi][ni], (const uint32_t*)&a4, bfr[ni]);
            }
        }
    }

    // ---- Phase B epilogue: direct aligned STG.64 (skip = D, out = D + x) ----
    {
        float* outb  = out  + (size_t)b * CC * TLEN;
        float* skipb = skip + (size_t)b * CC * TLEN;
#pragma unroll
        for (int mi = 0; mi < 2; mi++)
#pragma unroll
            for (int ni = 0; ni < 4; ni++) {
                int np0 = wn * 32 + ni * 8 + 2 * qc;     // even
                int t0  = tbase + np0;                   // even -> float2 aligned
                int r0  = wm * 32 + mi * 16 + grp;
                if (np0 < NTO && t0 + 1 < TLEN) {
#pragma unroll
                    for (int h = 0; h < 2; h++) {
                        size_t off = (size_t)(r0 + h * 8) * TLEN + t0;
                        float d0 = acc[mi][ni][h * 2], d1 = acc[mi][ni][h * 2 + 1];
                        float2 xr = *(const float2*)(xb + off);
                        *(float2*)(skipb + off) = make_float2(d0, d1);
                        *(float2*)(outb  + off) = make_float2(d0 + xr.x, d1 + xr.y);
                    }
                } else if (np0 < NTO && t0 < TLEN) {     // last valid single column
#pragma unroll
                    for (int h = 0; h < 2; h++) {
                        size_t off = (size_t)(r0 + h * 8) * TLEN + t0;
                        float d0 = acc[mi][ni][h * 2];
                        skipb[off] = d0;
                        outb[off]  = d0 + xb[off];
                    }
                }
            }
    }
}

extern "C" void kernel_launch(void* const* d_in, const int* in_sizes, int n_in,
                              void* d_out, int out_size) {
    const float* x  = (const float*)d_in[0];
    const float* wf = (const float*)d_in[1];
    const float* wg = (const float*)d_in[2];
    const float* ws = (const float*)d_in[3];

    float* out  = (float*)d_out;
    float* skip = out + (size_t)BB * CC * TLEN;

    cudaFuncSetAttribute(k_fused, cudaFuncAttributeMaxDynamicSharedMemorySize, SMEMF);

    k_transpose<<<(3 * 4096 + 255) / 256, 256>>>(wf, wg, ws);

    dim3 grid(NBLK, BB);
    k_fused<<<grid, 256, SMEMF>>>(x, out, skip);
}

// round 13
// speedup vs baseline: 5.6724x; 1.0347x over previous
#include <cuda_runtime.h>
#include <cuda_fp16.h>
#include <cstdint>

#define BB 32
#define CC 128
#define TLEN 16000
#define NTO 62               // valid output columns per block (EVEN -> aligned float2 stores)
#define NBLK 259             // ceil(16000/62)

// smem (u32 units): xt = x tile, t-major half2{cin,cin+1}, stride 68 (banks 4g+q bijective)
//                   ot = o tile, t-major half2{cout,cout+1}, stride 68, 65 rows (row 64 = pad)
#define XTS   68
#define XROWS 68
#define OT_U32_OFF (XROWS * XTS)             // 4624
#define SMEMF ((XROWS * XTS + 65 * XTS) * 4) // 36176 B

__device__ uint4 g_wtA[3 * 4096];            // fp16 fragment-packed weights

// ---------------- helpers ----------------
__device__ __forceinline__ uint32_t h2pack(float lo, float hi) {
    __half2 h = __floats2half2_rn(lo, hi);
    return *(uint32_t*)&h;
}

__device__ __forceinline__ void mma_f16(float* d, const uint32_t* a, const uint32_t* b) {
    asm volatile(
        "mma.sync.aligned.m16n8k16.row.col.f32.f16.f16.f32 "
        "{%0,%1,%2,%3}, {%4,%5,%6,%7}, {%8,%9}, {%0,%1,%2,%3};"
        : "+f"(d[0]), "+f"(d[1]), "+f"(d[2]), "+f"(d[3])
        : "r"(a[0]), "r"(a[1]), "r"(a[2]), "r"(a[3]), "r"(b[0]), "r"(b[1]));
}

// ---------------- weight fragment pre-pack (fp16) ----------------
// uint4 idx = conv*4096 + c*1024 + kf*256 + mi*128 + wm*32 + lane
// tap = kf>>1, cb = c*32 + (kf&1)*16 + qc*2, r0 = wm*32 + mi*16 + grp
__global__ void k_transpose(const float* __restrict__ wf,
                            const float* __restrict__ wg,
                            const float* __restrict__ ws) {
    int idx = blockIdx.x * 256 + threadIdx.x;
    if (idx >= 3 * 4096) return;
    int lane = idx & 31;
    int wm   = (idx >> 5) & 3;
    int mi   = (idx >> 7) & 1;
    int kf   = (idx >> 8) & 3;
    int c    = (idx >> 10) & 3;
    int conv = idx >> 12;
    int grp = lane >> 2, qc = lane & 3;
    int r0  = wm * 32 + mi * 16 + grp;
    int cb  = c * 32 + (kf & 1) * 16 + qc * 2;
    int tap = kf >> 1;
    const float* src = (conv == 0) ? wf : ((conv == 1) ? wg : ws);
#define WV(r, ci) src[((r) * CC + (ci)) * 2 + tap]
    uint4 v;
    v.x = h2pack(WV(r0, cb),     WV(r0, cb + 1));
    v.y = h2pack(WV(r0 + 8, cb), WV(r0 + 8, cb + 1));
    v.z = h2pack(WV(r0, cb + 8),     WV(r0, cb + 9));
    v.w = h2pack(WV(r0 + 8, cb + 8), WV(r0 + 8, cb + 9));
#undef WV
    g_wtA[idx] = v;
}

// ---------------- fused: f/g convs -> gated act (smem) -> skip conv -> residual ----
__global__ __launch_bounds__(256, 2) void k_fused(const float* __restrict__ x,
                                                  float* __restrict__ out,
                                                  float* __restrict__ skip) {
    extern __shared__ uint32_t smu[];
    uint32_t* xt = smu;                  // [68 j][68 stride], j=0 <-> t = tbase-3
    uint32_t* ot = smu + OT_U32_OFF;     // [65 j][68 stride], j   <-> t = tbase-1+j

    const int tid  = threadIdx.x;
    const int wid  = tid >> 5;
    const int lane = tid & 31;
    const int grp  = lane >> 2;
    const int qc   = lane & 3;
    const int wm   = wid & 3;
    const int wn   = wid >> 2;
    const int b     = blockIdx.y;
    const int tbase = blockIdx.x * NTO;  // EVEN
    const float* xb = x + (size_t)b * CC * TLEN;

    // ---- stage x tile once (68 rows x 64 cin-pairs = 4352 = 17*256) ----
#pragma unroll
    for (int it = 0; it < 17; it++) {
        int idx = it * 256 + tid;
        int cp = idx / XROWS;            // 0..63
        int j  = idx - cp * XROWS;       // 0..67 (lane-contiguous -> coalesced LDG)
        int t  = tbase - 3 + j;
        float lo = 0.f, hi = 0.f;
        if (t >= 0 && t < TLEN) {
            lo = xb[(size_t)(2 * cp) * TLEN + t];
            hi = xb[(size_t)(2 * cp + 1) * TLEN + t];
        }
        xt[j * XTS + cp] = h2pack(lo, hi);
    }
    __syncthreads();

    // ================= Phase A: f/g GEMMs (fragments direct from xt) ====
    float accf[2][4][4], accg[2][4][4];
#pragma unroll
    for (int mi = 0; mi < 2; mi++)
#pragma unroll
        for (int ni = 0; ni < 4; ni++)
#pragma unroll
            for (int i = 0; i < 4; i++) { accf[mi][ni][i] = 0.f; accg[mi][ni][i] = 0.f; }

    {
        const uint4* gwf = g_wtA + (wm * 32 + lane);
        const uint4* gwg = gwf + 4096;
        const uint32_t* xtw = xt + (wn * 32 + grp) * XTS + qc;  // base for this thread's B frags
        for (int c = 0; c < 4; c++) {
#pragma unroll
            for (int kf = 0; kf < 4; kf++) {
                const int tap2 = (kf >> 1) * 2;
                const int cpb  = c * 16 + (kf & 1) * 8;
                uint32_t bfr[4][2];
#pragma unroll
                for (int ni = 0; ni < 4; ni++) {
                    const uint32_t* p = xtw + (ni * 8 + tap2) * XTS + cpb;
                    bfr[ni][0] = p[0];
                    bfr[ni][1] = p[4];
                }
#pragma unroll
                for (int mi = 0; mi < 2; mi++) {
                    uint4 af = gwf[c * 1024 + kf * 256 + mi * 128];
                    uint4 ag = gwg[c * 1024 + kf * 256 + mi * 128];
#pragma unroll
                    for (int ni = 0; ni < 4; ni++) {
                        mma_f16(accf[mi][ni], (const uint32_t*)&af, bfr[ni]);
                        mma_f16(accg[mi][ni], (const uint32_t*)&ag, bfr[ni]);
                    }
                }
            }
        }
    }

    // zero ot pad row 64 (feeds masked columns only; must be finite)
    if (tid < XTS) ot[64 * XTS + tid] = 0;

    // ---- Phase A epilogue: gated act -> ot via shfl pack ----
    {
#pragma unroll
        for (int mi = 0; mi < 2; mi++)
#pragma unroll
            for (int ni = 0; ni < 4; ni++) {
                float f0 = accf[mi][ni][0], f1 = accf[mi][ni][1];
                float f2 = accf[mi][ni][2], f3 = accf[mi][ni][3];
                float g0 = accg[mi][ni][0], g1 = accg[mi][ni][1];
                float g2 = accg[mi][ni][2], g3 = accg[mi][ni][3];
                float v0 = (1.f - __fdividef(2.f, 1.f + __expf(2.f * f0))) * __fdividef(1.f, 1.f + __expf(-g0));
                float v1 = (1.f - __fdividef(2.f, 1.f + __expf(2.f * f1))) * __fdividef(1.f, 1.f + __expf(-g1));
                float v2 = (1.f - __fdividef(2.f, 1.f + __expf(2.f * f2))) * __fdividef(1.f, 1.f + __expf(-g2));
                float v3 = (1.f - __fdividef(2.f, 1.f + __expf(2.f * f3))) * __fdividef(1.f, 1.f + __expf(-g3));
                float u0 = __shfl_xor_sync(0xFFFFFFFF, v0, 4);
                float u1 = __shfl_xor_sync(0xFFFFFFFF, v1, 4);
                float u2 = __shfl_xor_sync(0xFFFFFFFF, v2, 4);
                float u3 = __shfl_xor_sync(0xFFFFFFFF, v3, 4);
                int t0 = wn * 32 + ni * 8 + 2 * qc;
                int cp = wm * 16 + mi * 8 + (grp >> 1);
                if (!(grp & 1)) {          // even grp owns column t0
                    ot[t0 * XTS + cp]     = h2pack(v0, u0);   // rows r0, r0+1
                    ot[t0 * XTS + cp + 4] = h2pack(v2, u2);   // rows r0+8, r0+9
                } else {                   // odd grp owns column t0+1
                    ot[(t0 + 1) * XTS + cp]     = h2pack(u1, v1);
                    ot[(t0 + 1) * XTS + cp + 4] = h2pack(u3, v3);
                }
            }
    }
    __syncthreads();   // ot complete, cross-warp visible

    // ================= Phase B: skip GEMM, 4 warps x (32 rows x 64 cols) =================
    // One warp per SMSP; per-SMSP HMMA cycles unchanged, A-weight traffic halved.
    if (wid < 4) {
        float acc[2][8][4];
#pragma unroll
        for (int mi = 0; mi < 2; mi++)
#pragma unroll
            for (int ni = 0; ni < 8; ni++)
#pragma unroll
                for (int i = 0; i < 4; i++) acc[mi][ni][i] = 0.f;

        const uint4* gws = g_wtA + 2 * 4096 + (wid * 32 + lane);
        const uint32_t* otw = ot + grp * XTS + qc;
        for (int c = 0; c < 4; c++) {
#pragma unroll
            for (int kf = 0; kf < 4; kf++) {
                const int tap = kf >> 1;
                const int cpb = c * 16 + (kf & 1) * 8;
                uint32_t bfr[8][2];
#pragma unroll
                for (int ni = 0; ni < 8; ni++) {
                    const uint32_t* p = otw + (ni * 8 + tap) * XTS + cpb;
                    bfr[ni][0] = p[0];
                    bfr[ni][1] = p[4];
                }
#pragma unroll
                for (int mi = 0; mi < 2; mi++) {
                    uint4 a4 = gws[c * 1024 + kf * 256 + mi * 128];
#pragma unroll
                    for (int ni = 0; ni < 8; ni++)
                        mma_f16(acc[mi][ni], (const uint32_t*)&a4, bfr[ni]);
                }
            }
        }

        // ---- Phase B epilogue: direct aligned STG.64 (skip = D, out = D + x) ----
        float* outb  = out  + (size_t)b * CC * TLEN;
        float* skipb = skip + (size_t)b * CC * TLEN;
#pragma unroll
        for (int mi = 0; mi < 2; mi++)
#pragma unroll
            for (int ni = 0; ni < 8; ni++) {
                int np0 = ni * 8 + 2 * qc;               // even, 0..62
                int t0  = tbase + np0;                   // even -> float2 aligned
                int r0  = wid * 32 + mi * 16 + grp;
                if (np0 < NTO && t0 + 1 < TLEN) {
#pragma unroll
                    for (int h = 0; h < 2; h++) {
                        size_t off = (size_t)(r0 + h * 8) * TLEN + t0;
                        float d0 = acc[mi][ni][h * 2], d1 = acc[mi][ni][h * 2 + 1];
                        float2 xr = *(const float2*)(xb + off);
                        *(float2*)(skipb + off) = make_float2(d0, d1);
                        *(float2*)(outb  + off) = make_float2(d0 + xr.x, d1 + xr.y);
                    }
                } else if (np0 < NTO && t0 < TLEN) {     // last valid single column
#pragma unroll
                    for (int h = 0; h < 2; h++) {
                        size_t off = (size_t)(r0 + h * 8) * TLEN + t0;
                        float d0 = acc[mi][ni][h * 2];
                        skipb[off] = d0;
                        outb[off]  = d0 + xb[off];
                    }
                }
            }
    }
}

extern "C" void kernel_launch(void* const* d_in, const int* in_sizes, int n_in,
                              void* d_out, int out_size) {
    const float* x  = (const float*)d_in[0];
    const float* wf = (const float*)d_in[1];
    const float* wg = (const float*)d_in[2];
    const float* ws = (const float*)d_in[3];

    float* out  = (float*)d_out;
    float* skip = out + (size_t)BB * CC * TLEN;

    cudaFuncSetAttribute(k_fused, cudaFuncAttributeMaxDynamicSharedMemorySize, SMEMF);

    k_transpose<<<(3 * 4096 + 255) / 256, 256>>>(wf, wg, ws);

    dim3 grid(NBLK, BB);
    k_fused<<<grid, 256, SMEMF>>>(x, out, skip);
}